// round 5
// baseline (speedup 1.0000x reference)
#include <cuda_runtime.h>
#include <math.h>

// Problem constants
#define N_RES 2048
#define D_IN  128
#define T_SEQ 2048
#define GRID  128      // CTAs, all wave-1 resident -- required for grid barrier
#define ROWS  16       // reservoir rows per CTA
#define NTH   512      // 16 warps; each warp owns a 128-column chunk, each lane 4 cols
#define SP_STRIDE 18   // sPart row stride (bank-conflict-free finisher reads)

// Scratch (allocation-free rule: __device__ globals)
__device__ float    g_U[(size_t)T_SEQ * N_RES];  // 16 MB: U = input @ W_in^T
__device__ unsigned g_flags[GRID * 8];           // per-CTA step counters, 32B stride

__global__ void esn_zero_kernel() {
    int i = threadIdx.x;
    if (i < GRID) g_flags[i * 8] = 0u;
}

__device__ __forceinline__ unsigned ld_acq(const unsigned* p) {
    unsigned v;
    asm volatile("ld.acquire.gpu.global.u32 %0, [%1];" : "=r"(v) : "l"(p) : "memory");
    return v;
}
__device__ __forceinline__ void st_rel(unsigned* p, unsigned v) {
    asm volatile("st.release.gpu.global.u32 [%0], %1;" :: "l"(p), "r"(v) : "memory");
}
// Packed fp32x2 FMA (Blackwell; ptxas never auto-fuses this from C++)
__device__ __forceinline__ unsigned long long ffma2(unsigned long long a,
                                                    unsigned long long b,
                                                    unsigned long long c) {
    unsigned long long d;
    asm("fma.rn.f32x2 %0, %1, %2, %3;" : "=l"(d) : "l"(a), "l"(b), "l"(c));
    return d;
}
__device__ __forceinline__ float hadd2(unsigned long long a) {
    unsigned lo, hi;
    asm("mov.b64 {%0,%1}, %2;" : "=r"(lo), "=r"(hi) : "l"(a));
    return __uint_as_float(lo) + __uint_as_float(hi);
}
// L2-path 16B load as two packed f32x2
__device__ __forceinline__ void ldcg_v2u64(const void* p,
                                           unsigned long long& a, unsigned long long& b) {
    asm volatile("ld.global.cg.v2.u64 {%0,%1}, [%2];" : "=l"(a), "=l"(b) : "l"(p));
}

__global__ void __launch_bounds__(NTH, 1)
esn_kernel(const float* __restrict__ inp,    // (T, D_IN)
           const float* __restrict__ Win,    // (N_RES, D_IN)
           const float* __restrict__ Wres,   // (N_RES, N_RES)
           float*       __restrict__ out)    // (T, N_RES): row t is state x_t
{
    __shared__ float sWin[ROWS * D_IN];          // 8 KB (prologue only)
    __shared__ float sPart[ROWS * SP_STRIDE];    // [row][warp] partials

    const int tid  = threadIdx.x;
    const int bid  = blockIdx.x;
    const int row0 = bid * ROWS;
    const int warp = tid >> 5;
    const int lane = tid & 31;
    const int cb   = warp * 128 + lane * 4;      // this thread's 4-column base

    // ---- stage W_in slice into SMEM ----
    for (int i = tid; i < ROWS * D_IN; i += NTH)
        sWin[i] = Win[(size_t)row0 * D_IN + i];
    __syncthreads();

    // ---- prologue: U[t][row0..row0+15] for all t (chunked, low reg pressure) ----
    for (int it = 0; it < T_SEQ / NTH; ++it) {
        const int t = it * NTH + tid;
        float acc[ROWS];
        #pragma unroll
        for (int r = 0; r < ROWS; ++r) acc[r] = 0.f;
        #pragma unroll
        for (int c = 0; c < 4; ++c) {            // 32-col input chunks
            float4 xin[8];
            const float4* ip = (const float4*)(inp + (size_t)t * D_IN + c * 32);
            #pragma unroll
            for (int k = 0; k < 8; ++k) xin[k] = ip[k];
            #pragma unroll
            for (int r = 0; r < ROWS; ++r) {
                const float4* wr = (const float4*)(sWin + r * D_IN + c * 32);
                #pragma unroll
                for (int k = 0; k < 8; ++k) {
                    float4 w = wr[k];
                    acc[r] += w.x * xin[k].x + w.y * xin[k].y
                            + w.z * xin[k].z + w.w * xin[k].w;
                }
            }
        }
        #pragma unroll
        for (int r = 0; r < ROWS; ++r)
            g_U[(size_t)t * N_RES + row0 + r] = acc[r];
    }

    // ---- W_res slice into registers: 16 rows x 4 cols = 64 regs (32 x f32x2) ----
    unsigned long long wv[ROWS][2];
    #pragma unroll
    for (int r = 0; r < ROWS; ++r) {
        ulonglong2 q = *(const ulonglong2*)(Wres + (size_t)(row0 + r) * N_RES + cb);
        wv[r][0] = q.x; wv[r][1] = q.y;
    }
    __syncthreads();   // g_U complete & visible CTA-wide

    const float c = 0.022097086912079612f;  // 1/sqrt(2048)

    for (int t = 0; t < T_SEQ; ++t) {
        // ---- wait: every CTA has published step t-1 ----
        if (t > 0 && tid < GRID) {
            const unsigned* fp = &g_flags[tid * 8];
            while (ld_acq(fp) < (unsigned)t) { }
        }
        __syncthreads();                                   // (a)

        float uval = 0.f;
        if (warp == 0 && lane < ROWS)
            uval = __ldcg(g_U + (size_t)t * N_RES + row0 + lane);  // prefetch

        if (t > 0) {
            // this thread's 4 values of x_{t-1} (L2 path, one LDG.128)
            unsigned long long x0, x1;
            ldcg_v2u64(out + (size_t)(t - 1) * N_RES + cb, x0, x1);

            // 16 rows x 2 packed FMAs; butterfly-reduce each row across the warp
            #pragma unroll
            for (int r = 0; r < ROWS; ++r) {
                unsigned long long a = ffma2(wv[r][0], x0, 0ull);
                a = ffma2(wv[r][1], x1, a);
                float s = hadd2(a);
                s += __shfl_xor_sync(0xffffffffu, s, 1);
                s += __shfl_xor_sync(0xffffffffu, s, 2);
                s += __shfl_xor_sync(0xffffffffu, s, 4);
                s += __shfl_xor_sync(0xffffffffu, s, 8);
                s += __shfl_xor_sync(0xffffffffu, s, 16);
                if (lane == r) sPart[r * SP_STRIDE + warp] = s;
            }
        }
        __syncthreads();                                   // (b)

        // ---- finishers: warp 0, lanes 0..15 (one row each) ----
        if (warp == 0) {
            if (lane < ROWS) {
                float pre = uval;
                if (t > 0) {
                    const float2* pp = (const float2*)(sPart + lane * SP_STRIDE);
                    #pragma unroll
                    for (int j = 0; j < 8; ++j) {
                        float2 v = pp[j];
                        pre += v.x + v.y;
                    }
                }
                __stcg(out + (size_t)t * N_RES + row0 + lane, erff(pre) * c);
            }
            __syncwarp();
            if (tid == 0) st_rel(&g_flags[bid * 8], (unsigned)(t + 1));
        }
        // other warps run ahead to the next poll; sync (a) keeps sPart safe
    }
}

extern "C" void kernel_launch(void* const* d_in, const int* in_sizes, int n_in,
                              void* d_out, int out_size) {
    const float* inp  = (const float*)d_in[0];   // input_data (2048,128)
    const float* Win  = (const float*)d_in[1];   // W_in       (2048,128)
    const float* Wres = (const float*)d_in[2];   // W_res      (2048,2048)
    float* out = (float*)d_out;                  // (2048,2048) float32

    esn_zero_kernel<<<1, 128>>>();
    esn_kernel<<<GRID, NTH>>>(inp, Win, Wres, out);
}